// round 4
// baseline (speedup 1.0000x reference)
#include <cuda_runtime.h>
#include <cstdint>

#define NTAGS 48
#define SEQ 512
#define BSZ 64
#define TILE (NTAGS*NTAGS)          // 2304 floats
#define TILE_BYTES (TILE*4)         // 9216 B
#define STAGES 4
#define NTHREADS 384
#define NGROUPS 8
#define ROWS_PER (NTAGS/NGROUPS)    // 6
#define CHUNKS (TILE_BYTES/16)      // 576 x 16B
#define LOG2E_F 1.4426950408889634f
#define LN2_F   0.6931471805599453f
#define START_TAG 46
#define END_TAG 47
#define EPS_F   1e-12f

__device__ double g_loss_accum;

__device__ __forceinline__ float ex2f(float x){
    float y; asm("ex2.approx.ftz.f32 %0, %1;" : "=f"(y) : "f"(x)); return y;
}
__device__ __forceinline__ float lg2f(float x){
    float y; asm("lg2.approx.ftz.f32 %0, %1;" : "=f"(y) : "f"(x)); return y;
}
__device__ __forceinline__ void cp16(uint32_t s, const void* g){
    asm volatile("cp.async.cg.shared.global [%0], [%1], 16;" :: "r"(s), "l"(g));
}
__device__ __forceinline__ void cp_commit(){ asm volatile("cp.async.commit_group;"); }
__device__ __forceinline__ void cp_wait2(){ asm volatile("cp.async.wait_group 2;"); }

__global__ __launch_bounds__(NTHREADS, 1)
void crf_fwd_kernel(const float* __restrict__ tr,
                    const int* __restrict__ tgt)     // int32! (JAX x64-off downgrades int64)
{
    __shared__ __align__(16) float buf[STAGES][TILE];   // 36864 B
    __shared__ float2 part[NGROUPS][NTAGS];             // 3072 B  (lm, ls)
    __shared__ float forw[NTAGS];                       // 192 B   (absolute fp32, like ref)
    __shared__ unsigned char tg[SEQ];                   // 512 B

    const int tid = threadIdx.x;
    const int b   = blockIdx.x;
    const float* trb = tr + (size_t)b * SEQ * TILE;

    // preload targets (int32, values 0..45) — clamp defensively to [0,47]
    for (int i = tid; i < SEQ; i += NTHREADS){
        int v = tgt[(size_t)b * SEQ + i];
        tg[i] = (unsigned char)(((unsigned)v < NTAGS) ? v : 0);
    }

    const int g = tid / NTAGS;            // row-group 0..7
    const int j = tid - g * NTAGS;        // column  0..47
    const int c0 = tid;                   // chunk ids for cp.async
    const int c1 = tid + NTHREADS;

    // prologue: prefetch tiles 0..2
    #pragma unroll
    for (int t = 0; t < STAGES - 1; ++t){
        uint32_t sb = (uint32_t)__cvta_generic_to_shared(&buf[t][0]);
        const float* gb = trb + (size_t)t * TILE;
        cp16(sb + c0 * 16, gb + c0 * 4);
        if (c1 < CHUNKS) cp16(sb + c1 * 16, gb + c1 * 4);
        cp_commit();
    }

    double tscore = 0.0;  // thread 0 only

    for (int t = 0; t < SEQ; ++t){
        cp_wait2();
        __syncthreads();                  // barrier A: tile t ready, forw(t-1) visible

        // prefetch tile t+3 into the stage freed after step t-1
        {
            int tn = t + STAGES - 1;
            if (tn < SEQ){
                int st = tn & (STAGES - 1);
                uint32_t sb = (uint32_t)__cvta_generic_to_shared(&buf[st][0]);
                const float* gb = trb + (size_t)tn * TILE;
                cp16(sb + c0 * 16, gb + c0 * 4);
                if (c1 < CHUNKS) cp16(sb + c1 * 16, gb + c1 * 4);
            }
            cp_commit();                  // uniform group count every iteration
        }

        const float* tile = &buf[t & (STAGES - 1)][0];

        if (t == 0){
            if (tid == 0) tscore += (double)tile[START_TAG * NTAGS + tg[0]];
            if (tid < NTAGS) forw[tid] = tile[START_TAG * NTAGS + tid];  // forw0
            __syncthreads();              // barrier B (uniform count)
        } else {
            // ---- phase A: per-group max + exp-sum over 6 rows (mirrors ref LSE) ----
            const int r0 = g * ROWS_PER;
            float tmp[ROWS_PER];
            float lm = -3.402823466e+38f;
            #pragma unroll
            for (int k = 0; k < ROWS_PER; ++k){
                tmp[k] = forw[r0 + k] + tile[(r0 + k) * NTAGS + j];
                lm = fmaxf(lm, tmp[k]);
            }
            float ls = 0.f;
            #pragma unroll
            for (int k = 0; k < ROWS_PER; ++k)
                ls += ex2f((tmp[k] - lm) * LOG2E_F);
            part[g][j] = make_float2(lm, ls);

            if (tid == 0) tscore += (double)tile[tg[t-1] * NTAGS + tg[t]];
            __syncthreads();              // barrier B: partials visible, tile free

            // ---- phase B: combine 8 (max,sum) pairs per column ----
            if (tid < NTAGS){
                float2 p0 = part[0][tid], p1 = part[1][tid];
                float2 p2 = part[2][tid], p3 = part[3][tid];
                float2 p4 = part[4][tid], p5 = part[5][tid];
                float2 p6 = part[6][tid], p7 = part[7][tid];
                float m = fmaxf(fmaxf(fmaxf(p0.x, p1.x), fmaxf(p2.x, p3.x)),
                                fmaxf(fmaxf(p4.x, p5.x), fmaxf(p6.x, p7.x)));
                float s = p0.y * ex2f((p0.x - m) * LOG2E_F)
                        + p1.y * ex2f((p1.x - m) * LOG2E_F)
                        + p2.y * ex2f((p2.x - m) * LOG2E_F)
                        + p3.y * ex2f((p3.x - m) * LOG2E_F)
                        + p4.y * ex2f((p4.x - m) * LOG2E_F)
                        + p5.y * ex2f((p5.x - m) * LOG2E_F)
                        + p6.y * ex2f((p6.x - m) * LOG2E_F)
                        + p7.y * ex2f((p7.x - m) * LOG2E_F);
                // forw_j = log(s + EPS) + m   (exactly the reference's update)
                forw[tid] = fmaf(lg2f(s + EPS_F), LN2_F, m);
            }
        }
    }

    __syncthreads();
    if (tid == 0){
        double loss = (double)forw[END_TAG] - tscore;
        atomicAdd(&g_loss_accum, loss);
    }
}

__global__ void zero_kernel(){ g_loss_accum = 0.0; }
__global__ void finalize_kernel(float* o){ *o = (float)(g_loss_accum * (1.0 / (double)BSZ)); }

extern "C" void kernel_launch(void* const* d_in, const int* in_sizes, int n_in,
                              void* d_out, int out_size)
{
    const float* tr  = (const float*)d_in[0];
    const int*   tgt = (const int*)d_in[1];
    float*       out = (float*)d_out;

    zero_kernel<<<1, 1>>>();
    crf_fwd_kernel<<<BSZ, NTHREADS>>>(tr, tgt);
    finalize_kernel<<<1, 1>>>(out);
}

// round 5
// speedup vs baseline: 1.6549x; 1.6549x over previous
#include <cuda_runtime.h>
#include <cstdint>

#define NTAGS 48
#define SEQ 512
#define BSZ 64
#define NTRANS (NTAGS*NTAGS)         // 2304 floats per gmem tile
#define ROWSTRIDE 52                 // padded smem row stride (floats): conflict-free
#define TILE_PAD (NTAGS*ROWSTRIDE)   // 2496 floats per stage
#define STAGES 4
#define NTHREADS 384
#define CHUNKS (NTAGS*12)            // 576 x 16B data chunks per tile
#define LOG2E_F 1.4426950408889634f
#define LN2_F   0.6931471805599453f
#define START_TAG 46
#define END_TAG 47
#define MARGIN 24.0f

__device__ float g_part[BSZ];

__device__ __forceinline__ float ex2f(float x){
    float y; asm("ex2.approx.ftz.f32 %0, %1;" : "=f"(y) : "f"(x)); return y;
}
__device__ __forceinline__ float lg2f(float x){
    float y; asm("lg2.approx.ftz.f32 %0, %1;" : "=f"(y) : "f"(x)); return y;
}
__device__ __forceinline__ void cp16(uint32_t s, const void* g){
    asm volatile("cp.async.cg.shared.global [%0], [%1], 16;" :: "r"(s), "l"(g));
}
__device__ __forceinline__ void cp_commit(){ asm volatile("cp.async.commit_group;"); }
__device__ __forceinline__ void cp_wait2(){ asm volatile("cp.async.wait_group 2;"); }

__global__ __launch_bounds__(NTHREADS, 1)
void crf_fwd_kernel(const float* __restrict__ tr,
                    const int* __restrict__ tgt)
{
    __shared__ __align__(16) float buf[STAGES][TILE_PAD];  // 39936 B
    __shared__ float forwbuf[2][NTAGS];                    // double-buffered forw
    __shared__ float Mbuf[2];                              // double-buffered normalizer
    __shared__ unsigned char tg[SEQ];

    const int tid = threadIdx.x;
    const int b   = blockIdx.x;
    const float* trb = tr + (size_t)b * SEQ * NTRANS;

    for (int i = tid; i < SEQ; i += NTHREADS){
        int v = tgt[(size_t)b * SEQ + i];
        tg[i] = (unsigned char)(((unsigned)v < NTAGS) ? v : 0);
    }

    const int w   = tid >> 5;
    const int l   = tid & 31;
    const int col = (w << 2) + (l & 3);   // column 0..47 (warp w owns 4 cols)
    const int q   = l >> 2;               // row subgroup 0..7 (rows q, q+8, ..., q+40)

    const int c0 = tid;
    const int c1 = tid + NTHREADS;
    const int r0a = c0 / 12, o0a = c0 % 12;          // chunk -> (row, 16B-offset)
    const int r1a = c1 / 12, o1a = c1 % 12;

    auto prefetch = [&](int t){
        uint32_t sb = (uint32_t)__cvta_generic_to_shared(&buf[t & (STAGES-1)][0]);
        const float* gb = trb + (size_t)t * NTRANS;
        cp16(sb + (uint32_t)(r0a * (ROWSTRIDE*4) + o0a * 16), gb + c0 * 4);
        if (c1 < CHUNKS)
            cp16(sb + (uint32_t)(r1a * (ROWSTRIDE*4) + o1a * 16), gb + c1 * 4);
    };

    // prologue: tiles 0..2
    prefetch(0); cp_commit();
    prefetch(1); cp_commit();
    prefetch(2); cp_commit();

    cp_wait2();                // tile 0 complete
    __syncthreads();
    prefetch(3); cp_commit();

    // ---- t = 0 init ----
    if (tid < NTAGS) forwbuf[0][tid] = buf[0][START_TAG * ROWSTRIDE + tid];
    float tscore = 0.f;
    unsigned char prev = tg[0];
    if (tid == 0){
        tscore = buf[0][START_TAG * ROWSTRIDE + prev];
        Mbuf[0] = buf[0][START_TAG * ROWSTRIDE + 0] + MARGIN;
    }

    for (int t = 1; t < SEQ; ++t){
        cp_wait2();
        __syncthreads();       // tile t ready; forw/M of t-1 visible; stage (t+3)&3 free

        if (t + 3 < SEQ) prefetch(t + 3);
        cp_commit();           // uniform group count

        const float* tile = &buf[t & (STAGES-1)][0];
        const float* fw   = forwbuf[(t-1) & 1];
        const float  M    = Mbuf[(t-1) & 1];
        const float  nML2E = -M * LOG2E_F;

        // 6 elements per thread: e_k = exp2((tr + forw[r] - M) * log2e)
        float e0, e1, e2, e3, e4, e5;
        {
            float f;
            f  = fmaf(fw[q     ], LOG2E_F, nML2E);
            e0 = ex2f(fmaf(tile[(q     ) * ROWSTRIDE + col], LOG2E_F, f));
            f  = fmaf(fw[q +  8], LOG2E_F, nML2E);
            e1 = ex2f(fmaf(tile[(q +  8) * ROWSTRIDE + col], LOG2E_F, f));
            f  = fmaf(fw[q + 16], LOG2E_F, nML2E);
            e2 = ex2f(fmaf(tile[(q + 16) * ROWSTRIDE + col], LOG2E_F, f));
            f  = fmaf(fw[q + 24], LOG2E_F, nML2E);
            e3 = ex2f(fmaf(tile[(q + 24) * ROWSTRIDE + col], LOG2E_F, f));
            f  = fmaf(fw[q + 32], LOG2E_F, nML2E);
            e4 = ex2f(fmaf(tile[(q + 32) * ROWSTRIDE + col], LOG2E_F, f));
            f  = fmaf(fw[q + 40], LOG2E_F, nML2E);
            e5 = ex2f(fmaf(tile[(q + 40) * ROWSTRIDE + col], LOG2E_F, f));
        }
        float s = ((e0 + e1) + (e2 + e3)) + (e4 + e5);
        s += __shfl_xor_sync(0xffffffffu, s, 4);
        s += __shfl_xor_sync(0xffffffffu, s, 8);
        s += __shfl_xor_sync(0xffffffffu, s, 16);

        float fnew = fmaf(lg2f(s), LN2_F, M);   // = log(sum exp(x)) exactly (scalar M)
        if (q == 0) forwbuf[t & 1][col] = fnew;

        if (tid == 0){
            Mbuf[t & 1] = fnew + MARGIN;        // fnew here is column 0's value
            unsigned char cur = tg[t];
            tscore += tile[(int)prev * ROWSTRIDE + cur];
            prev = cur;
        }
    }

    __syncthreads();
    if (tid == 0)
        g_part[b] = forwbuf[(SEQ-1) & 1][END_TAG] - tscore;
}

__global__ void finalize_kernel(float* o){
    int t = threadIdx.x;                      // 32 threads
    double v = (double)g_part[t] + (double)g_part[t + 32];
    #pragma unroll
    for (int m = 16; m > 0; m >>= 1)
        v += __shfl_xor_sync(0xffffffffu, v, m);
    if (t == 0) *o = (float)(v * (1.0 / (double)BSZ));
}

extern "C" void kernel_launch(void* const* d_in, const int* in_sizes, int n_in,
                              void* d_out, int out_size)
{
    const float* tr  = (const float*)d_in[0];
    const int*   tgt = (const int*)d_in[1];
    float*       out = (float*)d_out;

    crf_fwd_kernel<<<BSZ, NTHREADS>>>(tr, tgt);
    finalize_kernel<<<1, 32>>>(out);
}